// round 15
// baseline (speedup 1.0000x reference)
#include <cuda_runtime.h>

#define NUM_SEGMENTS 512
#define NCTAS 128
#define SEGS_PER_CTA (NUM_SEGMENTS / NCTAS)   // 4
#define THREADS 1024
#define ROWG (THREADS / 16)                   // 64 row-groups, 16 float4 lanes per 64-float row

__device__ __forceinline__ int lower_bound_i32(const int* __restrict__ b, int n, int v) {
    int lo = 0, hi = n;
    while (lo < hi) {
        int mid = (lo + hi) >> 1;
        if (b[mid] < v) lo = mid + 1; else hi = mid;
    }
    return lo;
}

// NOTE: no dynamic smem pad. 64 regs x 1024 threads = full RF -> 1 CTA/SM is
// enforced by registers, and the small static smem leaves ~200 KB of L1D
// carveout so pass-2's reverse-order re-read catches the pass-1 tail in L1.

__global__ __launch_bounds__(THREADS, 1)
void pairnorm_kernel(const float4* __restrict__ x4,
                     const int* __restrict__ batch,   // int32 (JAX x64 disabled)
                     float4* __restrict__ out4,
                     int N)
{
    __shared__ float4 s_red[ROWG * 16];          // 16 KB tree-reduce scratch
    __shared__ float  s_warp[THREADS / 32];
    __shared__ float4 s_mean[16];
    __shared__ float  s_inv;
    __shared__ int    s_bound[SEGS_PER_CTA + 1];

    const int tid  = threadIdx.x;
    const int seg0 = (int)blockIdx.x * SEGS_PER_CTA;

    if (tid <= SEGS_PER_CTA)
        s_bound[tid] = lower_bound_i32(batch, N, seg0 + tid);
    __syncthreads();

    const int lane16 = tid & 15;
    const int rg     = tid >> 4;

    // "cur" segment = stats ready, awaiting pass-2. Empty initially.
    int curLo = 0, curHi = 0;
    float4 mean = make_float4(0.f, 0.f, 0.f, 0.f);
    float  inv  = 0.f;

    for (int i = 0; i < SEGS_PER_CTA; i++) {
        const int nLo = s_bound[i];
        const int nHi = s_bound[i + 1];

        // ---- Fused loop: pass-1(seg i) DRAM stream + pass-2(seg i-1) ----
        // pass-2 runs in REVERSE so the freshest pass-1 lines hit L1.
        float4 acc = make_float4(0.f, 0.f, 0.f, 0.f);
        float ssq = 0.f;

        int rn = nLo + rg;
        int rc;
        {
            int start = curLo + rg;
            rc = (start < curHi) ? start + ((curHi - 1 - start) / ROWG) * ROWG
                                 : curLo - 1;
        }
        const int itN = (nHi  > nLo  + rg) ? (nHi  - (nLo  + rg) + ROWG - 1) / ROWG : 0;
        const int itC = (curHi > curLo + rg) ? (curHi - (curLo + rg) + ROWG - 1) / ROWG : 0;
        const int iters = itN > itC ? itN : itC;

        #pragma unroll 4
        for (int k = 0; k < iters; k++) {
            if (rn < nHi) {                       // pass-1: stats stream (DRAM)
                float4 v = x4[(size_t)rn * 16 + lane16];
                acc.x += v.x; acc.y += v.y; acc.z += v.z; acc.w += v.w;
                ssq += v.x * v.x + v.y * v.y + v.z * v.z + v.w * v.w;
                rn += ROWG;
            }
            if (rc >= curLo) {                    // pass-2: L1/L2-hot re-read
                float4 v = x4[(size_t)rc * 16 + lane16];
                float4 o;
                o.x = (v.x - mean.x) * inv;
                o.y = (v.y - mean.y) * inv;
                o.z = (v.z - mean.z) * inv;
                o.w = (v.w - mean.w) * inv;
                __stcs(&out4[(size_t)rc * 16 + lane16], o);  // dead data: evict-first
                rc -= ROWG;
            }
        }

        // ---- Reduce stats for segment i ----
        s_red[rg * 16 + lane16] = acc;
        #pragma unroll
        for (int off = 16; off > 0; off >>= 1)
            ssq += __shfl_xor_sync(0xffffffffu, ssq, off);
        if ((tid & 31) == 0) s_warp[tid >> 5] = ssq;
        __syncthreads();

        #pragma unroll
        for (int off = ROWG / 2; off >= 1; off >>= 1) {
            if (rg < off) {
                float4 a = s_red[rg * 16 + lane16];
                float4 b = s_red[(rg + off) * 16 + lane16];
                a.x += b.x; a.y += b.y; a.z += b.z; a.w += b.w;
                s_red[rg * 16 + lane16] = a;
            }
            __syncthreads();
        }

        if (tid == 0) {
            float tot = 0.f;
            #pragma unroll
            for (int w = 0; w < THREADS / 32; w++) tot += s_warp[w];
            const int cnt = nHi - nLo;
            const float invc = 1.f / (float)(cnt > 0 ? cnt : 1);
            float msq = 0.f;
            #pragma unroll
            for (int j = 0; j < 16; j++) {
                float4 m = s_red[j];
                m.x *= invc; m.y *= invc; m.z *= invc; m.w *= invc;
                s_mean[j] = m;
                msq += m.x * m.x + m.y * m.y + m.z * m.z + m.w * m.w;
            }
            // sum||x-m||^2 / cnt = sumsq/cnt - ||m||^2
            float var = fmaxf(tot * invc - msq, 0.f);
            s_inv = rsqrtf(var);
        }
        __syncthreads();

        mean = s_mean[lane16];
        inv  = s_inv;
        curLo = nLo;
        curHi = nHi;
    }

    // ---- Final pass-2 for the last segment (reverse, L1-hot tail first) ----
    {
        int start = curLo + rg;
        int rc = (start < curHi) ? start + ((curHi - 1 - start) / ROWG) * ROWG
                                 : curLo - 1;
        #pragma unroll 4
        for (; rc >= curLo; rc -= ROWG) {
            float4 v = x4[(size_t)rc * 16 + lane16];
            float4 o;
            o.x = (v.x - mean.x) * inv;
            o.y = (v.y - mean.y) * inv;
            o.z = (v.z - mean.z) * inv;
            o.w = (v.w - mean.w) * inv;
            __stcs(&out4[(size_t)rc * 16 + lane16], o);
        }
    }
}

extern "C" void kernel_launch(void* const* d_in, const int* in_sizes, int n_in,
                              void* d_out, int out_size)
{
    const float4* x4    = (const float4*)d_in[0];
    const int*    batch = (const int*)d_in[1];
    float4*       out4  = (float4*)d_out;
    const int N = in_sizes[1];   // 1,000,000 rows; D = 64 fixed

    pairnorm_kernel<<<NCTAS, THREADS>>>(x4, batch, out4, N);
}

// round 16
// speedup vs baseline: 1.5716x; 1.5716x over previous
#include <cuda_runtime.h>

#define NUM_SEGMENTS 512
#define THREADS_A 256
#define ROWG_A (THREADS_A / 16)   // 16 row-groups of 16 lanes

__device__ float g_mean4[NUM_SEGMENTS * 64]; // per-seg mean, 64 floats each
__device__ float g_inv[NUM_SEGMENTS];        // per-seg 1/sqrt(mean centered sqnorm)

__device__ __forceinline__ int lower_bound_i32(const int* __restrict__ b, int n, int v) {
    int lo = 0, hi = n;
    while (lo < hi) {
        int mid = (lo + hi) >> 1;
        if (b[mid] < v) lo = mid + 1; else hi = mid;
    }
    return lo;
}

// ---------------- Kernel A: per-segment stats (one CTA per segment) ----------
__global__ __launch_bounds__(THREADS_A)
void stats_kernel(const float4* __restrict__ x4,
                  const int* __restrict__ batch,   // int32 (JAX x64 disabled)
                  int N)
{
    __shared__ float4 s_red[ROWG_A * 16];
    __shared__ float  s_warp[THREADS_A / 32];
    __shared__ int    s_lo, s_hi;

    const int tid = threadIdx.x;
    const int seg = (int)blockIdx.x;

    if (tid == 0)  s_lo = lower_bound_i32(batch, N, seg);
    if (tid == 32) s_hi = lower_bound_i32(batch, N, seg + 1);
    __syncthreads();
    const int lo = s_lo, hi = s_hi;

    const int lane16 = tid & 15;
    const int rg     = tid >> 4;

    float4 acc = make_float4(0.f, 0.f, 0.f, 0.f);
    float ssq = 0.f;
    #pragma unroll 8
    for (int r = lo + rg; r < hi; r += ROWG_A) {
        float4 v = x4[(size_t)r * 16 + lane16];
        acc.x += v.x; acc.y += v.y; acc.z += v.z; acc.w += v.w;
        ssq += v.x * v.x + v.y * v.y + v.z * v.z + v.w * v.w;
    }
    s_red[rg * 16 + lane16] = acc;

    #pragma unroll
    for (int off = 16; off > 0; off >>= 1)
        ssq += __shfl_xor_sync(0xffffffffu, ssq, off);
    if ((tid & 31) == 0) s_warp[tid >> 5] = ssq;
    __syncthreads();

    #pragma unroll
    for (int off = ROWG_A / 2; off >= 1; off >>= 1) {
        if (rg < off) {
            float4 a = s_red[rg * 16 + lane16];
            float4 b = s_red[(rg + off) * 16 + lane16];
            a.x += b.x; a.y += b.y; a.z += b.z; a.w += b.w;
            s_red[rg * 16 + lane16] = a;
        }
        __syncthreads();
    }

    if (tid == 0) {
        float tot = 0.f;
        #pragma unroll
        for (int w = 0; w < THREADS_A / 32; w++) tot += s_warp[w];
        const int cnt = hi - lo;
        const float invc = 1.f / (float)(cnt > 0 ? cnt : 1);
        float msq = 0.f;
        #pragma unroll
        for (int i = 0; i < 16; i++) {
            float4 m = s_red[i];
            m.x *= invc; m.y *= invc; m.z *= invc; m.w *= invc;
            ((float4*)g_mean4)[seg * 16 + i] = m;
            msq += m.x * m.x + m.y * m.y + m.z * m.z + m.w * m.w;
        }
        // sum||x-m||^2 / cnt = sumsq/cnt - ||m||^2
        float var = fmaxf(tot * invc - msq, 0.f);
        g_inv[seg] = rsqrtf(var);
    }
}

// ---------------- Kernel B: grid-stride normalize (no barriers) --------------
#define THREADS_B 256
#define GRID_B (148 * 16)

__global__ __launch_bounds__(THREADS_B)
void normalize_kernel(const float4* __restrict__ x4,
                      const int* __restrict__ batch,
                      float4* __restrict__ out4,
                      int n4)   // N * 16 float4 elements
{
    const int stride = GRID_B * THREADS_B;
    int i = (int)blockIdx.x * THREADS_B + (int)threadIdx.x;

    for (; i < n4; i += stride) {
        const int row  = i >> 4;
        const int lane = i & 15;
        const int seg  = __ldg(&batch[row]);          // L1 broadcast (16 thr/row)
        const float4 m = __ldg(&((const float4*)g_mean4)[seg * 16 + lane]);
        const float inv = __ldg(&g_inv[seg]);
        float4 v = __ldcs(&x4[i]);                    // dead after this: evict-first
        float4 o;
        o.x = (v.x - m.x) * inv;
        o.y = (v.y - m.y) * inv;
        o.z = (v.z - m.z) * inv;
        o.w = (v.w - m.w) * inv;
        __stcs(&out4[i], o);                          // streaming store
    }
}

extern "C" void kernel_launch(void* const* d_in, const int* in_sizes, int n_in,
                              void* d_out, int out_size)
{
    const float4* x4    = (const float4*)d_in[0];
    const int*    batch = (const int*)d_in[1];
    float4*       out4  = (float4*)d_out;
    const int N = in_sizes[1];     // 1,000,000 rows; D = 64 fixed
    const int n4 = N * 16;         // float4 count

    stats_kernel<<<NUM_SEGMENTS, THREADS_A>>>(x4, batch, N);
    normalize_kernel<<<GRID_B, THREADS_B>>>(x4, batch, out4, n4);
}